// round 1
// baseline (speedup 1.0000x reference)
#include <cuda_runtime.h>
#include <float.h>

typedef unsigned long long U64;

// ---------------- scratch (no allocations allowed) ----------------
__device__ float g_dist0[10 * 253 * 253];
__device__ float g_dist1[5 * 127 * 127];
__device__ float g_partial[16];

// ---------------- packed f32x2 helpers ----------------
__device__ __forceinline__ U64 add2(U64 a, U64 b) {
    U64 r;
    asm("add.rn.f32x2 %0, %1, %2;" : "=l"(r) : "l"(a), "l"(b));
    return r;
}
__device__ __forceinline__ U64 pack2(float lo, float hi) {
    U64 r;
    asm("mov.b64 %0, {%1, %2};" : "=l"(r) : "f"(lo), "f"(hi));
    return r;
}
__device__ __forceinline__ float2 unpack2(U64 v) {
    float lo, hi;
    asm("mov.b64 {%0, %1}, %2;" : "=f"(lo), "=f"(hi) : "l"(v));
    return make_float2(lo, hi);
}

#define ABS2_MASK 0x7FFFFFFF7FFFFFFFULL

// =====================================================================
// Scale 0: C=64, H=W=256, ps=3, Hm=Wm=253, 10 targets (5 per grid.z)
// dist(T,h,w) = sum_c sum_{i,j} |src[c,h+i,w+j] - tgt[c,th+i,tw+j]|
// =====================================================================
#define TILE_W 32
#define TILE_H 16
#define SM_W 34
#define SM_H 18
#define TPG 5

__global__ __launch_bounds__(256, 2) void dist0_kernel(
    const float* __restrict__ src, const float* __restrict__ tgt,
    const int* __restrict__ pos)
{
    __shared__ U64 s_tile[SM_H * SM_W];        // channel-pair interleaved tile
    __shared__ U64 s_negt[32 * TPG * 9];       // -t, [cpair][T][off] packed pairs

    const int tid = threadIdx.x;
    const int tx = blockIdx.x * TILE_W;
    const int ty = blockIdx.y * TILE_H;
    const int tb = blockIdx.z * TPG;

    // Pre-negated target patch values, channel-pair packed
    for (int i = tid; i < 32 * TPG * 9; i += 256) {
        int o  = i % 9;
        int T  = (i / 9) % TPG;
        int cp = i / (9 * TPG);
        int th = pos[(tb + T) * 2 + 0];
        int tw = pos[(tb + T) * 2 + 1];
        int di = o / 3, dj = o % 3;
        const float* b = tgt + (th + di) * 256 + (tw + dj);
        s_negt[i] = pack2(-b[(2 * cp) * 65536], -b[(2 * cp + 1) * 65536]);
    }

    const int thx = tid & 31;        // 0..31 -> w
    const int thy = tid >> 5;        // 0..7  -> h pair
    const int w  = tx + thx;
    const int h0 = ty + 2 * thy;
    const bool act0 = (w < 253) && (h0 < 253);
    const bool act1 = (w < 253) && (h0 + 1 < 253);

    U64 acc0[TPG], acc1[TPG];
#pragma unroll
    for (int T = 0; T < TPG; T++) { acc0[T] = 0ULL; acc1[T] = 0ULL; }  // (0.f,0.f)

    for (int cp = 0; cp < 32; cp++) {
        __syncthreads();   // protects s_tile reuse; first iter also covers s_negt
        const float* s0 = src + (2 * cp) * 65536;
        const float* s1 = src + (2 * cp + 1) * 65536;
        for (int i = tid; i < SM_H * SM_W; i += 256) {
            int r = i / SM_W, cx = i - r * SM_W;
            int y = ty + r, x = tx + cx;
            float v0 = 0.f, v1 = 0.f;
            if (y < 256 && x < 256) { int off = y * 256 + x; v0 = s0[off]; v1 = s1[off]; }
            s_tile[i] = pack2(v0, v1);
        }
        __syncthreads();

        // 4 rows x 3 cols window (2 vertical pixels share 3 middle rows)
        U64 sv[4][3];
        const int r0 = 2 * thy;
#pragma unroll
        for (int r = 0; r < 4; r++)
#pragma unroll
            for (int j = 0; j < 3; j++)
                sv[r][j] = s_tile[(r0 + r) * SM_W + thx + j];

        const U64* tp = s_negt + cp * TPG * 9;
#pragma unroll
        for (int T = 0; T < TPG; T++) {
#pragma unroll
            for (int o = 0; o < 9; o++) {
                const int di = o / 3, dj = o % 3;
                U64 nt = tp[T * 9 + o];                       // broadcast LDS.64
                U64 d0 = add2(sv[di][dj],     nt) & ABS2_MASK;
                U64 d1 = add2(sv[di + 1][dj], nt) & ABS2_MASK;
                acc0[T] = add2(acc0[T], d0);
                acc1[T] = add2(acc1[T], d1);
            }
        }
    }

#pragma unroll
    for (int T = 0; T < TPG; T++) {
        float2 a0 = unpack2(acc0[T]);
        float2 a1 = unpack2(acc1[T]);
        if (act0) g_dist0[(tb + T) * 64009 + h0 * 253 + w]       = a0.x + a0.y;
        if (act1) g_dist0[(tb + T) * 64009 + (h0 + 1) * 253 + w] = a1.x + a1.y;
    }
}

// =====================================================================
// Scale 1: C=128, H=W=128, ps=1, Hm=Wm=127, 5 targets
// =====================================================================
__global__ __launch_bounds__(256) void dist1_kernel(
    const float* __restrict__ src, const float* __restrict__ tgt,
    const int* __restrict__ pos)
{
    __shared__ U64 s_negt[64 * 5];   // [cpair][T]
    const int tid = threadIdx.x;
    for (int i = tid; i < 64 * 5; i += 256) {
        int T = i % 5, cp = i / 5;
        int th = pos[T * 2 + 0], tw = pos[T * 2 + 1];
        const float* b = tgt + th * 128 + tw;
        s_negt[i] = pack2(-b[(2 * cp) * 16384], -b[(2 * cp + 1) * 16384]);
    }
    __syncthreads();

    const int p = blockIdx.x * 256 + tid;
    if (p >= 16129) return;
    const int h = p / 127, w = p - h * 127;
    const float* sp = src + h * 128 + w;

    U64 acc[5];
#pragma unroll
    for (int T = 0; T < 5; T++) acc[T] = 0ULL;

    for (int cp = 0; cp < 64; cp++) {
        U64 s = pack2(sp[(2 * cp) * 16384], sp[(2 * cp + 1) * 16384]);
#pragma unroll
        for (int T = 0; T < 5; T++) {
            U64 d = add2(s, s_negt[cp * 5 + T]) & ABS2_MASK;
            acc[T] = add2(acc[T], d);
        }
    }
#pragma unroll
    for (int T = 0; T < 5; T++) {
        float2 a = unpack2(acc[T]);
        g_dist1[T * 16129 + p] = a.x + a.y;
    }
}

// =====================================================================
// Top-5 smallest per target map, scaled partial sums
// blocks 0..9 -> scale0 targets, 10..14 -> scale1 targets
// =====================================================================
__device__ __forceinline__ void ins5(float& a0, float& a1, float& a2, float& a3,
                                     float& a4, float v)
{
    if (v < a4) {
        a4 = v;
        float t;
        if (a4 < a3) { t = a3; a3 = a4; a4 = t; }
        if (a3 < a2) { t = a2; a2 = a3; a3 = t; }
        if (a2 < a1) { t = a1; a1 = a2; a2 = t; }
        if (a1 < a0) { t = a0; a0 = a1; a1 = t; }
    }
}

__global__ __launch_bounds__(1024) void topk_kernel()
{
    __shared__ float sm[1024 * 5];
    const int t = blockIdx.x;
    const int tid = threadIdx.x;

    const float* d;
    int n;
    float scale;
    if (t < 10) { d = g_dist0 + t * 64009;        n = 64009; scale = 1.0f / (576.0f * 5.0f * 10.0f); }
    else        { d = g_dist1 + (t - 10) * 16129; n = 16129; scale = 1.0f / (128.0f * 5.0f * 10.0f); }

    float a0 = FLT_MAX, a1 = FLT_MAX, a2 = FLT_MAX, a3 = FLT_MAX, a4 = FLT_MAX;
    for (int i = tid; i < n; i += 1024)
        ins5(a0, a1, a2, a3, a4, d[i]);

    sm[tid * 5 + 0] = a0; sm[tid * 5 + 1] = a1; sm[tid * 5 + 2] = a2;
    sm[tid * 5 + 3] = a3; sm[tid * 5 + 4] = a4;
    __syncthreads();

    for (int stride = 512; stride > 0; stride >>= 1) {
        if (tid < stride) {
            const float* o = &sm[(tid + stride) * 5];
#pragma unroll
            for (int k = 0; k < 5; k++) ins5(a0, a1, a2, a3, a4, o[k]);
            sm[tid * 5 + 0] = a0; sm[tid * 5 + 1] = a1; sm[tid * 5 + 2] = a2;
            sm[tid * 5 + 3] = a3; sm[tid * 5 + 4] = a4;
        }
        __syncthreads();
    }

    if (tid == 0)
        g_partial[t] = (a0 + a1 + a2 + a3 + a4) * scale;
}

__global__ void finalize_kernel(float* out)
{
    float s = 0.f;
#pragma unroll
    for (int i = 0; i < 15; i++) s += g_partial[i];
    out[0] = s;
}

// =====================================================================
extern "C" void kernel_launch(void* const* d_in, const int* in_sizes, int n_in,
                              void* d_out, int out_size)
{
    const float* src0 = (const float*)d_in[0];
    const float* tgt0 = (const float*)d_in[1];
    const float* src1 = (const float*)d_in[2];
    const float* tgt1 = (const float*)d_in[3];
    const int*   pos0 = (const int*)d_in[4];
    const int*   pos1 = (const int*)d_in[5];

    dim3 g0(8, 16, 2);   // ceil(253/32) x ceil(253/16) x (10 targets / 5)
    dist0_kernel<<<g0, 256>>>(src0, tgt0, pos0);
    dist1_kernel<<<64, 256>>>(src1, tgt1, pos1);
    topk_kernel<<<15, 1024>>>();
    finalize_kernel<<<1, 1>>>((float*)d_out);
}

// round 2
// speedup vs baseline: 1.3101x; 1.3101x over previous
#include <cuda_runtime.h>
#include <float.h>

typedef unsigned long long U64;

// ---------------- scratch (no allocations allowed) ----------------
#define D0_STRIDE 64012   // 64009 padded to mult of 4 (float4 alignment)
#define D1_STRIDE 16132   // 16129 padded
__device__ float g_dist0[10 * D0_STRIDE];
__device__ float g_dist1[5 * D1_STRIDE];
__device__ float g_partial[16];
__device__ int   g_count;          // zero-init; self-reset each replay

// ---------------- packed f32x2 helpers ----------------
__device__ __forceinline__ U64 add2(U64 a, U64 b) {
    U64 r;
    asm("add.rn.f32x2 %0, %1, %2;" : "=l"(r) : "l"(a), "l"(b));
    return r;
}
__device__ __forceinline__ U64 pack2(float lo, float hi) {
    U64 r;
    asm("mov.b64 %0, {%1, %2};" : "=l"(r) : "f"(lo), "f"(hi));
    return r;
}
__device__ __forceinline__ float2 unpack2(U64 v) {
    float lo, hi;
    asm("mov.b64 {%0, %1}, %2;" : "=f"(lo), "=f"(hi) : "l"(v));
    return make_float2(lo, hi);
}

#define ABS2_MASK 0x7FFFFFFF7FFFFFFFULL

// =====================================================================
// Fused distance kernel.
//   grid = (8, 16, 3), 256 threads
//   z in {0,1}: scale0 (C=64,H=W=256,ps=3,Hm=253), 5 targets per z
//   z == 2   : scale1 (C=128,H=W=128,ps=1,Hm=127), flat CTA id < 64
// =====================================================================
#define TILE_W 32
#define TILE_H 16
#define SM_W 34
#define SM_H 18
#define SM_N (SM_W * SM_H)   // 612
#define TPG 5

__global__ __launch_bounds__(256, 3) void dist_kernel(
    const float* __restrict__ src0, const float* __restrict__ tgt0,
    const int* __restrict__ pos0,
    const float* __restrict__ src1, const float* __restrict__ tgt1,
    const int* __restrict__ pos1)
{
    __shared__ U64 s_negt[32 * TPG * 10];        // padded [cp][T][10]
    __shared__ U64 s_tile[2][SM_N];              // double-buffered tile

    const int tid = threadIdx.x;

    // ---------------- scale-1 branch ----------------
    if (blockIdx.z == 2) {
        const int flat = blockIdx.y * 8 + blockIdx.x;
        if (flat >= 64) return;
        // reuse s_negt storage for the 5-target, 64-cpair table
        U64* negt1 = s_negt;                     // needs 320 U64
        for (int i = tid; i < 64 * 5; i += 256) {
            int T = i % 5, cp = i / 5;
            int th = pos1[T * 2 + 0], tw = pos1[T * 2 + 1];
            const float* b = tgt1 + th * 128 + tw;
            negt1[i] = pack2(-b[(2 * cp) * 16384], -b[(2 * cp + 1) * 16384]);
        }
        __syncthreads();

        const int p = flat * 256 + tid;
        if (p >= 16129) return;
        const int h = p / 127, w = p - h * 127;
        const float* sp = src1 + h * 128 + w;

        U64 acc[5];
#pragma unroll
        for (int T = 0; T < 5; T++) acc[T] = 0ULL;

        for (int cp = 0; cp < 64; cp++) {
            U64 s = pack2(sp[(2 * cp) * 16384], sp[(2 * cp + 1) * 16384]);
#pragma unroll
            for (int T = 0; T < 5; T++) {
                U64 d = add2(s, negt1[cp * 5 + T]) & ABS2_MASK;
                acc[T] = add2(acc[T], d);
            }
        }
#pragma unroll
        for (int T = 0; T < 5; T++) {
            float2 a = unpack2(acc[T]);
            g_dist1[T * D1_STRIDE + p] = a.x + a.y;
        }
        return;
    }

    // ---------------- scale-0 branch ----------------
    const int tx = blockIdx.x * TILE_W;
    const int ty = blockIdx.y * TILE_H;
    const int tb = blockIdx.z * TPG;

    // Pre-negated target patch values, channel-pair packed, padded stride 10
    for (int i = tid; i < 32 * TPG * 9; i += 256) {
        int o  = i % 9;
        int T  = (i / 9) % TPG;
        int cp = i / (9 * TPG);
        int th = pos0[(tb + T) * 2 + 0];
        int tw = pos0[(tb + T) * 2 + 1];
        int di = o / 3, dj = o % 3;
        const float* b = tgt0 + (th + di) * 256 + (tw + dj);
        s_negt[cp * (TPG * 10) + T * 10 + o] =
            pack2(-b[(2 * cp) * 65536], -b[(2 * cp + 1) * 65536]);
    }

    // Per-thread fill slots (3 per thread: tid, tid+256, tid+512)
    int  goff[3];
    bool gval[3];
#pragma unroll
    for (int k = 0; k < 3; k++) {
        int i = tid + k * 256;
        int r = i / SM_W, c = i - r * SM_W;
        int y = ty + r, x = tx + c;
        gval[k] = (i < SM_N) && (y < 256) && (x < 256);
        goff[k] = y * 256 + x;
    }

    U64 pre[3];
    {   // prologue: fetch cp=0, store to buf 0
        const float* s = src0;   // cp = 0
#pragma unroll
        for (int k = 0; k < 3; k++)
            pre[k] = gval[k] ? pack2(s[goff[k]], s[goff[k] + 65536]) : 0ULL;
#pragma unroll
        for (int k = 0; k < 3; k++) {
            int i = tid + k * 256;
            if (i < SM_N) s_tile[0][i] = pre[k];
        }
    }
    __syncthreads();   // covers s_negt fill + buf0 store

    const int thx = tid & 31;        // w within tile
    const int thy = tid >> 5;        // vertical pixel pair
    const int w  = tx + thx;
    const int h0 = ty + 2 * thy;
    const bool act0 = (w < 253) && (h0 < 253);
    const bool act1 = (w < 253) && (h0 + 1 < 253);
    const int r0 = 2 * thy;

    U64 acc0[TPG], acc1[TPG];
#pragma unroll
    for (int T = 0; T < TPG; T++) { acc0[T] = 0ULL; acc1[T] = 0ULL; }

    for (int cp = 0; cp < 32; cp++) {
        // 1) issue next-tile global loads early (latency hidden under compute)
        if (cp + 1 < 32) {
            const float* s = src0 + (2 * (cp + 1)) * 65536;
#pragma unroll
            for (int k = 0; k < 3; k++)
                pre[k] = gval[k] ? pack2(s[goff[k]], s[goff[k] + 65536]) : 0ULL;
        }

        // 2) compute from current buffer
        const U64* buf = s_tile[cp & 1];
        U64 sv[4][3];
#pragma unroll
        for (int r = 0; r < 4; r++)
#pragma unroll
            for (int j = 0; j < 3; j++)
                sv[r][j] = buf[(r0 + r) * SM_W + thx + j];

        const U64* tp = s_negt + cp * (TPG * 10);
#pragma unroll
        for (int T = 0; T < TPG; T++) {
            const ulonglong2* tp2 = (const ulonglong2*)(tp + T * 10); // 16B aligned
#pragma unroll
            for (int o2 = 0; o2 < 4; o2++) {
                ulonglong2 q = tp2[o2];                 // LDS.128 broadcast
                {
                    const int o = 2 * o2, di = o / 3, dj = o % 3;
                    U64 d0 = add2(sv[di][dj],     q.x) & ABS2_MASK;
                    U64 d1 = add2(sv[di + 1][dj], q.x) & ABS2_MASK;
                    acc0[T] = add2(acc0[T], d0);
                    acc1[T] = add2(acc1[T], d1);
                }
                {
                    const int o = 2 * o2 + 1, di = o / 3, dj = o % 3;
                    U64 d0 = add2(sv[di][dj],     q.y) & ABS2_MASK;
                    U64 d1 = add2(sv[di + 1][dj], q.y) & ABS2_MASK;
                    acc0[T] = add2(acc0[T], d0);
                    acc1[T] = add2(acc1[T], d1);
                }
            }
            {   // o = 8 (di=2, dj=2)
                U64 nt = tp[T * 10 + 8];
                U64 d0 = add2(sv[2][2], nt) & ABS2_MASK;
                U64 d1 = add2(sv[3][2], nt) & ABS2_MASK;
                acc0[T] = add2(acc0[T], d0);
                acc1[T] = add2(acc1[T], d1);
            }
        }

        // 3) commit prefetched tile to the other buffer
        if (cp + 1 < 32) {
            U64* nb = s_tile[(cp + 1) & 1];
#pragma unroll
            for (int k = 0; k < 3; k++) {
                int i = tid + k * 256;
                if (i < SM_N) nb[i] = pre[k];
            }
            __syncthreads();
        }
    }

#pragma unroll
    for (int T = 0; T < TPG; T++) {
        float2 a0 = unpack2(acc0[T]);
        float2 a1 = unpack2(acc1[T]);
        if (act0) g_dist0[(tb + T) * D0_STRIDE + h0 * 253 + w]       = a0.x + a0.y;
        if (act1) g_dist0[(tb + T) * D0_STRIDE + (h0 + 1) * 253 + w] = a1.x + a1.y;
    }
}

// =====================================================================
// Top-5 smallest per target + fused finalize (last-block pattern)
// blocks 0..9 -> scale0 targets, 10..14 -> scale1
// =====================================================================
__device__ __forceinline__ void ins5(float& a0, float& a1, float& a2, float& a3,
                                     float& a4, float v)
{
    if (v < a4) {
        a4 = v;
        float t;
        if (a4 < a3) { t = a3; a3 = a4; a4 = t; }
        if (a3 < a2) { t = a2; a2 = a3; a3 = t; }
        if (a2 < a1) { t = a1; a1 = a2; a2 = t; }
        if (a1 < a0) { t = a0; a0 = a1; a1 = t; }
    }
}

__global__ __launch_bounds__(1024) void topk_kernel(float* __restrict__ out)
{
    __shared__ float sm[1024 * 5];
    const int t = blockIdx.x;
    const int tid = threadIdx.x;

    const float* d;
    int n;
    float scale;
    if (t < 10) { d = g_dist0 + t * D0_STRIDE;        n = 64009; scale = 1.0f / (576.0f * 5.0f * 10.0f); }
    else        { d = g_dist1 + (t - 10) * D1_STRIDE; n = 16129; scale = 1.0f / (128.0f * 5.0f * 10.0f); }

    const int n4 = n >> 2;                       // full float4 groups
    const float4* d4 = (const float4*)d;         // slab bases are 16B aligned

    float a0 = FLT_MAX, a1 = FLT_MAX, a2 = FLT_MAX, a3 = FLT_MAX, a4 = FLT_MAX;
    for (int i = tid; i < n4; i += 1024) {
        float4 v = d4[i];
        ins5(a0, a1, a2, a3, a4, v.x);
        ins5(a0, a1, a2, a3, a4, v.y);
        ins5(a0, a1, a2, a3, a4, v.z);
        ins5(a0, a1, a2, a3, a4, v.w);
    }
    if (tid == 0)                                 // tail (n % 4 == 1 here)
        for (int i = n4 * 4; i < n; i++) ins5(a0, a1, a2, a3, a4, d[i]);

    sm[tid * 5 + 0] = a0; sm[tid * 5 + 1] = a1; sm[tid * 5 + 2] = a2;
    sm[tid * 5 + 3] = a3; sm[tid * 5 + 4] = a4;
    __syncthreads();

    for (int stride = 512; stride > 0; stride >>= 1) {
        if (tid < stride) {
            const float* o = &sm[(tid + stride) * 5];
#pragma unroll
            for (int k = 0; k < 5; k++) ins5(a0, a1, a2, a3, a4, o[k]);
            sm[tid * 5 + 0] = a0; sm[tid * 5 + 1] = a1; sm[tid * 5 + 2] = a2;
            sm[tid * 5 + 3] = a3; sm[tid * 5 + 4] = a4;
        }
        __syncthreads();
    }

    if (tid == 0) {
        g_partial[t] = (a0 + a1 + a2 + a3 + a4) * scale;
        __threadfence();
        int old = atomicAdd(&g_count, 1);
        if (old == 14) {                          // last block finalizes
            volatile float* gp = g_partial;
            float s = 0.f;
#pragma unroll
            for (int i = 0; i < 15; i++) s += gp[i];   // fixed order: deterministic
            out[0] = s;
            g_count = 0;                          // reset for next graph replay
        }
    }
}

// =====================================================================
extern "C" void kernel_launch(void* const* d_in, const int* in_sizes, int n_in,
                              void* d_out, int out_size)
{
    const float* src0 = (const float*)d_in[0];
    const float* tgt0 = (const float*)d_in[1];
    const float* src1 = (const float*)d_in[2];
    const float* tgt1 = (const float*)d_in[3];
    const int*   pos0 = (const int*)d_in[4];
    const int*   pos1 = (const int*)d_in[5];

    dim3 g0(8, 16, 3);
    dist_kernel<<<g0, 256>>>(src0, tgt0, pos0, src1, tgt1, pos1);
    topk_kernel<<<15, 1024>>>((float*)d_out);
}